// round 1
// baseline (speedup 1.0000x reference)
#include <cuda_runtime.h>

#define TT 1024
#define BB 32
#define II 512
#define HH 512
#define GG 2048
#define NBLK 128
#define NTH 256
#define CK 128
#define NCHUNK 4
#define KPT 16

// shared memory layout (float offsets)
#define OFF_W    0        // 4 mats * 512 k * 16 rows (k-major)        = 32768
#define OFF_U    32768    // 128 k * 33 (padded batch)                 = 4224
#define OFF_V    36992    // 128 k * 33                                = 4224
#define OFF_RED  32768    // 512 outputs * 9 (aliases U/V region)      = 4608
#define OFF_H0   41216    // 2 * 512                                   = 1024
#define OFF_BIAS 42240    // 2 * 16
#define OFF_C    42272    // 2 * 4 * 32
#define OFF_C0   42528    // 2 * 4
#define OFF_M    42536    // 32 ints
#define SMEM_FLOATS 42568
#define SMEM_BYTES (SMEM_FLOATS * 4)

__device__ float g_h[2][2][BB][HH];   // [layer][parity][batch][unit]
__device__ unsigned g_cnt;
__device__ unsigned g_gen;

__device__ __forceinline__ void grid_sync() {
    __syncthreads();
    if (threadIdx.x == 0) {
        __threadfence();
        unsigned gen = *(volatile unsigned*)&g_gen;
        unsigned old = atomicAdd(&g_cnt, 1u);
        if (old == NBLK - 1) {
            *(volatile unsigned*)&g_cnt = 0u;
            __threadfence();
            atomicAdd(&g_gen, 1u);
        } else {
            while (*(volatile unsigned*)&g_gen == gen) {}
        }
        __threadfence();
    }
    __syncthreads();
}

__device__ __forceinline__ float sigf(float x) {
    return 1.0f / (1.0f + __expf(-x));
}

// One layer-phase: gates = U @ WmatA^T + V_masked @ WmatB^T + bias; LSTM cell update.
__device__ __forceinline__ void phase(
    float* __restrict__ sm,
    const int* __restrict__ mS,
    const float* __restrict__ h0l,          // h0 row for this layer (smem)
    const float* __restrict__ Ug,           // [32][512] global, unmasked
    const float* __restrict__ Vg,           // [32][512] global, masked by mS
    int matA, int matB, int l,
    float* __restrict__ hOut,               // &g_h[l][parOut][0][0]
    float* __restrict__ outT,               // out + t*B*H or nullptr
    float* __restrict__ hN, float* __restrict__ cN, bool last,
    int j0, int tid, int bq, int rq, int ks)
{
    float* wS   = sm + OFF_W;
    float* uS   = sm + OFF_U;
    float* vS   = sm + OFF_V;
    float* redS = sm + OFF_RED;
    float* cS   = sm + OFF_C;
    float* c0S  = sm + OFF_C0;
    float* biasS= sm + OFF_BIAS;

    float acc[16];
#pragma unroll
    for (int i = 0; i < 16; i++) acc[i] = 0.0f;

    for (int c = 0; c < NCHUNK; c++) {
        __syncthreads();   // previous consumers of uS/vS (or redS) done
        int kc0 = c * CK;
        // stage U and masked V chunk: 32 batches x 128 k
#pragma unroll
        for (int i = 0; i < 16; i++) {
            int f = i * NTH + tid;
            int b = f >> 7;
            int k = f & 127;
            int kg = kc0 + k;
            float uval = __ldcg(Ug + b * 512 + kg);
            float hv   = __ldcg(Vg + b * 512 + kg);
            uS[k * 33 + b] = uval;
            vS[k * 33 + b] = mS[b] ? h0l[kg] : hv;
        }
        __syncthreads();
        int kbase = ks * KPT;
        const float* wA = wS + (matA * 512 + kc0) * 16;
        const float* wB = wS + (matB * 512 + kc0) * 16;
#pragma unroll 4
        for (int kk = 0; kk < KPT; kk++) {
            int k = kbase + kk;
            const float* ua = uS + k * 33 + bq * 4;
            const float* va = vS + k * 33 + bq * 4;
            const float* wa = wA + k * 16 + rq * 4;
            const float* wb = wB + k * 16 + rq * 4;
            float au[4], av[4], aw[4], bw[4];
#pragma unroll
            for (int j = 0; j < 4; j++) { au[j] = ua[j]; av[j] = va[j]; aw[j] = wa[j]; bw[j] = wb[j]; }
#pragma unroll
            for (int i = 0; i < 4; i++)
#pragma unroll
                for (int j = 0; j < 4; j++)
                    acc[i * 4 + j] += aw[i] * au[j];
#pragma unroll
            for (int i = 0; i < 4; i++)
#pragma unroll
                for (int j = 0; j < 4; j++)
                    acc[i * 4 + j] += bw[i] * av[j];
        }
    }

    // ---- cross-k-slice reduction + LSTM cell update ----
    __syncthreads();   // all compute reads of uS/vS done (redS aliases them)
#pragma unroll
    for (int i = 0; i < 4; i++)
#pragma unroll
        for (int j = 0; j < 4; j++)
            redS[(((rq * 4 + i) * 32) + bq * 4 + j) * 9 + ks] = acc[i * 4 + j];
    __syncthreads();

    if (tid < 128) {
        int u = tid >> 5;
        int b = tid & 31;
        float pre[4];
#pragma unroll
        for (int g = 0; g < 4; g++) {
            float s = biasS[l * 16 + g * 4 + u];
#pragma unroll
            for (int q = 0; q < 8; q++)
                s += redS[((g * 4 + u) * 32 + b) * 9 + q];
            pre[g] = s;
        }
        float cp = cS[(l * 4 + u) * 32 + b];
        if (mS[b]) cp = c0S[l * 4 + u];
        float ig = sigf(pre[0]);
        float fg = sigf(pre[1]);
        float gg = tanhf(pre[2]);
        float og = sigf(pre[3]);
        float cn = fg * cp + ig * gg;
        float hn = og * tanhf(cn);
        cS[(l * 4 + u) * 32 + b] = cn;
        __stcg(hOut + b * HH + j0 + u, hn);
        if (outT) outT[b * HH + j0 + u] = hn;
        if (last) {
            hN[(l * BB + b) * HH + j0 + u] = hn;
            cN[(l * BB + b) * HH + j0 + u] = cn;
        }
    }
}

__global__ void __launch_bounds__(NTH, 1)
lstm_kernel(const float* __restrict__ x,
            const int* __restrict__ rmask,
            const float* __restrict__ w_ih,
            const float* __restrict__ w_hh,
            const float* __restrict__ b_ih,
            const float* __restrict__ b_hh,
            const float* __restrict__ h0,
            const float* __restrict__ c0,
            float* __restrict__ out)
{
    extern __shared__ float sm[];
    float* wS    = sm + OFF_W;
    float* h0S   = sm + OFF_H0;
    float* biasS = sm + OFF_BIAS;
    float* cS    = sm + OFF_C;
    float* c0S   = sm + OFF_C0;
    int*   mS    = (int*)(sm + OFF_M);

    const int tid = threadIdx.x;
    const int bid = blockIdx.x;
    const int j0 = bid * 4;

    const int bq = tid & 7;          // batch quad
    const int rq = (tid >> 3) & 3;   // gate
    const int ks = tid >> 5;         // k slice (warp id)

    // ---- one-time weight load: k-major, 16 rows per matrix ----
    // mats: 0=w_ih L0, 1=w_hh L0, 2=w_ih L1, 3=w_hh L1
    for (int f = tid; f < 4 * 16 * 512; f += NTH) {
        int k = f & 511;
        int mr = f >> 9;              // 0..63
        int m = mr >> 4;
        int r = mr & 15;
        int gate = r >> 2, u = r & 3;
        int row = gate * HH + j0 + u;
        int l = m >> 1;
        const float* src;
        if ((m & 1) == 0) src = w_ih + ((size_t)l * GG + row) * II + k;
        else              src = w_hh + ((size_t)l * GG + row) * HH + k;
        wS[(m * 512 + k) * 16 + r] = __ldg(src);
    }
    if (tid < 32) {
        int l = tid >> 4;
        int r = tid & 15;
        int gate = r >> 2, u = r & 3;
        int row = gate * HH + j0 + u;
        biasS[tid] = __ldg(b_ih + l * GG + row) + __ldg(b_hh + l * GG + row);
    }
    for (int f = tid; f < 2 * HH; f += NTH) h0S[f] = __ldg(h0 + f);
    if (tid < 8) {
        int l = tid >> 2, u = tid & 3;
        c0S[tid] = __ldg(c0 + l * HH + j0 + u);
    }
    __syncthreads();
    // init c state (c0 broadcast over batch)
    for (int f = tid; f < 2 * 4 * 32; f += NTH) {
        int l = f >> 7;
        int u = (f >> 5) & 3;
        cS[f] = c0S[l * 4 + u];
    }
    // init h state (parity 0) = h0 broadcast
    {
        int l = tid >> 7, b = (tid >> 2) & 31, u = tid & 3;
        __stcg(&g_h[l][0][b][j0 + u], h0S[l * HH + j0 + u]);
    }
    grid_sync();

    float* hN = out + (size_t)TT * BB * HH;
    float* cN = hN + 2 * BB * HH;

    for (int t = 0; t < TT; t++) {
        int par = t & 1;
        __syncthreads();  // prior epilogue readers of mS done
        if (tid < 32) mS[tid] = __ldg(rmask + t * BB + tid);
        bool last = (t == TT - 1);

        // phase 1: layer 0. U = x[t], V = masked h_l0(prev)
        phase(sm, mS, h0S,
              x + (size_t)t * BB * II,
              &g_h[0][par][0][0],
              0, 1, 0,
              &g_h[0][par ^ 1][0][0],
              nullptr, hN, cN, last,
              j0, tid, bq, rq, ks);

        grid_sync();

        // phase 2: layer 1. U = fresh h_l0, V = masked h_l1(prev)
        phase(sm, mS, h0S + HH,
              &g_h[0][par ^ 1][0][0],
              &g_h[1][par][0][0],
              2, 3, 1,
              &g_h[1][par ^ 1][0][0],
              out + (size_t)t * BB * HH, hN, cN, last,
              j0, tid, bq, rq, ks);
        // (no end-of-step grid sync needed: parity double-buffering makes the
        //  only cross-block hazards pass through the mid-step sync)
    }
}

extern "C" void kernel_launch(void* const* d_in, const int* in_sizes, int n_in,
                              void* d_out, int out_size) {
    const float* x    = (const float*)d_in[0];
    const int*   rm   = (const int*)d_in[1];
    const float* w_ih = (const float*)d_in[2];
    const float* w_hh = (const float*)d_in[3];
    const float* b_ih = (const float*)d_in[4];
    const float* b_hh = (const float*)d_in[5];
    const float* h0   = (const float*)d_in[6];
    const float* c0   = (const float*)d_in[7];
    float* out = (float*)d_out;

    cudaFuncSetAttribute(lstm_kernel, cudaFuncAttributeMaxDynamicSharedMemorySize, SMEM_BYTES);
    lstm_kernel<<<NBLK, NTH, SMEM_BYTES>>>(x, rm, w_ih, w_hh, b_ih, b_hh, h0, c0, out);
}

// round 3
// speedup vs baseline: 1.6679x; 1.6679x over previous
#include <cuda_runtime.h>

#define TT 1024
#define BB 32
#define II 512
#define HH 512
#define GG 2048
#define NBLK 128
#define NTH 512
#define CK 128
#define NCHUNK 4
#define KPT 8
#define NSLICE 16

// shared memory layout (float offsets)
#define OFF_W    0        // 4 mats * 512 k * 16 rows (k-major)        = 32768
#define OFF_STG  32768    // union: U(128*33) + V(128*33) = 8448  |  RED 512*17 = 8704
#define OFF_U    OFF_STG
#define OFF_V    (OFF_STG + 4224)
#define OFF_RED  OFF_STG
#define OFF_H0   41472    // 2 * 512
#define OFF_BIAS 42496    // 2 * 16
#define OFF_C    42528    // 2 * 4 * 32
#define OFF_C0   42784    // 2 * 4
#define OFF_M    42792    // 32 ints
#define SMEM_FLOATS 42824
#define SMEM_BYTES (SMEM_FLOATS * 4)

__device__ float g_h[2][2][BB][HH];   // [layer][parity][batch][unit]
__device__ unsigned g_cnt;
__device__ unsigned g_gen;

__device__ __forceinline__ void grid_sync() {
    __syncthreads();
    if (threadIdx.x == 0) {
        __threadfence();
        unsigned gen = *(volatile unsigned*)&g_gen;
        unsigned old = atomicAdd(&g_cnt, 1u);
        if (old == NBLK - 1) {
            *(volatile unsigned*)&g_cnt = 0u;
            __threadfence();
            atomicAdd(&g_gen, 1u);
        } else {
            while (*(volatile unsigned*)&g_gen == gen) { __nanosleep(20); }
        }
        __threadfence();
    }
    __syncthreads();
}

__device__ __forceinline__ float sigf(float x) {
    return 1.0f / (1.0f + __expf(-x));
}

// One layer-phase: gates = U @ WmatA^T + V_masked @ WmatB^T + bias; LSTM cell update.
__device__ __forceinline__ void phase(
    float* __restrict__ sm,
    const int* __restrict__ mS,
    const float* __restrict__ h0l,
    const float* __restrict__ Ug,           // [32][512] global, unmasked
    const float* __restrict__ Vg,           // [32][512] global, masked by mS
    int matA, int matB, int l,
    float* __restrict__ hOut,
    float* __restrict__ outT,
    float* __restrict__ hN, float* __restrict__ cN, bool last,
    int j0, int tid, int bq, int rq, int ks)
{
    float* wS   = sm + OFF_W;
    float* uS   = sm + OFF_U;
    float* vS   = sm + OFF_V;
    float* redS = sm + OFF_RED;
    float* cS   = sm + OFF_C;
    float* c0S  = sm + OFF_C0;
    float* biasS= sm + OFF_BIAS;

    float acc[16];
#pragma unroll
    for (int i = 0; i < 16; i++) acc[i] = 0.0f;

    // per-thread staging coords (8 elements per buffer)
    const int sk = tid & 127;               // k within chunk
    const int sb0 = tid >> 7;               // base b (i adds 4 per step)

    float ru[8], rv[8];
    // prefetch chunk 0
#pragma unroll
    for (int i = 0; i < 8; i++) {
        int b = i * 4 + sb0;
        float uval = __ldcg(Ug + b * 512 + sk);
        float hv   = __ldcg(Vg + b * 512 + sk);
        ru[i] = uval;
        rv[i] = mS[b] ? h0l[sk] : hv;
    }

    for (int c = 0; c < NCHUNK; c++) {
        __syncthreads();   // previous consumers of uS/vS done
        // store prefetched chunk
#pragma unroll
        for (int i = 0; i < 8; i++) {
            int b = i * 4 + sb0;
            uS[sk * 33 + b] = ru[i];
            vS[sk * 33 + b] = rv[i];
        }
        // prefetch next chunk (overlaps with compute of this chunk)
        if (c < NCHUNK - 1) {
            int kg = (c + 1) * CK + sk;
#pragma unroll
            for (int i = 0; i < 8; i++) {
                int b = i * 4 + sb0;
                float uval = __ldcg(Ug + b * 512 + kg);
                float hv   = __ldcg(Vg + b * 512 + kg);
                ru[i] = uval;
                rv[i] = mS[b] ? h0l[kg] : hv;
            }
        }
        __syncthreads();

        int kc0 = c * CK;
        int kbase = ks * KPT;
        const float* wA = wS + (matA * 512 + kc0) * 16;
        const float* wB = wS + (matB * 512 + kc0) * 16;
#pragma unroll
        for (int kk = 0; kk < KPT; kk++) {
            int k = kbase + kk;
            const float* ua = uS + k * 33 + bq * 4;
            const float* va = vS + k * 33 + bq * 4;
            const float* wa = wA + k * 16 + rq * 4;
            const float* wb = wB + k * 16 + rq * 4;
            float au[4], av[4], aw[4], bw[4];
#pragma unroll
            for (int j = 0; j < 4; j++) { au[j] = ua[j]; av[j] = va[j]; aw[j] = wa[j]; bw[j] = wb[j]; }
#pragma unroll
            for (int i = 0; i < 4; i++)
#pragma unroll
                for (int j = 0; j < 4; j++)
                    acc[i * 4 + j] += aw[i] * au[j];
#pragma unroll
            for (int i = 0; i < 4; i++)
#pragma unroll
                for (int j = 0; j < 4; j++)
                    acc[i * 4 + j] += bw[i] * av[j];
        }
    }

    // ---- cross-k-slice reduction + LSTM cell update ----
    __syncthreads();   // all compute reads of uS/vS done (redS aliases them)
#pragma unroll
    for (int i = 0; i < 4; i++)
#pragma unroll
        for (int j = 0; j < 4; j++)
            redS[(((rq * 4 + i) * 32) + bq * 4 + j) * 17 + ks] = acc[i * 4 + j];
    __syncthreads();

    if (tid < 128) {
        int u = tid >> 5;
        int b = tid & 31;
        float pre[4];
#pragma unroll
        for (int g = 0; g < 4; g++) {
            float s = biasS[l * 16 + g * 4 + u];
#pragma unroll
            for (int q = 0; q < NSLICE; q++)
                s += redS[((g * 4 + u) * 32 + b) * 17 + q];
            pre[g] = s;
        }
        float cp = cS[(l * 4 + u) * 32 + b];
        if (mS[b]) cp = c0S[l * 4 + u];
        float ig = sigf(pre[0]);
        float fg = sigf(pre[1]);
        float gg = tanhf(pre[2]);
        float og = sigf(pre[3]);
        float cn = fg * cp + ig * gg;
        float hn = og * tanhf(cn);
        cS[(l * 4 + u) * 32 + b] = cn;
        __stcg(hOut + b * HH + j0 + u, hn);
        if (outT) outT[b * HH + j0 + u] = hn;
        if (last) {
            hN[(l * BB + b) * HH + j0 + u] = hn;
            cN[(l * BB + b) * HH + j0 + u] = cn;
        }
    }
}

__global__ void __launch_bounds__(NTH, 1)
lstm_kernel(const float* __restrict__ x,
            const int* __restrict__ rmask,
            const float* __restrict__ w_ih,
            const float* __restrict__ w_hh,
            const float* __restrict__ b_ih,
            const float* __restrict__ b_hh,
            const float* __restrict__ h0,
            const float* __restrict__ c0,
            float* __restrict__ out)
{
    extern __shared__ float sm[];
    float* wS    = sm + OFF_W;
    float* h0S   = sm + OFF_H0;
    float* biasS = sm + OFF_BIAS;
    float* cS    = sm + OFF_C;
    float* c0S   = sm + OFF_C0;
    int*   mS    = (int*)(sm + OFF_M);

    const int tid = threadIdx.x;
    const int bid = blockIdx.x;
    const int j0 = bid * 4;

    const int bq = tid & 7;          // batch quad
    const int rq = (tid >> 3) & 3;   // row quad (gate)
    const int ks = tid >> 5;         // k slice (warp id), 0..15

    // ---- one-time weight load: k-major, 16 rows per matrix ----
    for (int f = tid; f < 4 * 16 * 512; f += NTH) {
        int k = f & 511;
        int mr = f >> 9;
        int m = mr >> 4;
        int r = mr & 15;
        int gate = r >> 2, u = r & 3;
        int row = gate * HH + j0 + u;
        int l = m >> 1;
        const float* src;
        if ((m & 1) == 0) src = w_ih + ((size_t)l * GG + row) * II + k;
        else              src = w_hh + ((size_t)l * GG + row) * HH + k;
        wS[(m * 512 + k) * 16 + r] = __ldg(src);
    }
    if (tid < 32) {
        int l = tid >> 4;
        int r = tid & 15;
        int gate = r >> 2, u = r & 3;
        int row = gate * HH + j0 + u;
        biasS[tid] = __ldg(b_ih + l * GG + row) + __ldg(b_hh + l * GG + row);
    }
    for (int f = tid; f < 2 * HH; f += NTH) h0S[f] = __ldg(h0 + f);
    if (tid < 8) {
        int l = tid >> 2, u = tid & 3;
        c0S[tid] = __ldg(c0 + l * HH + j0 + u);
    }
    __syncthreads();
    for (int f = tid; f < 2 * 4 * 32; f += NTH) {
        int l = f >> 7;
        int u = (f >> 5) & 3;
        cS[f] = c0S[l * 4 + u];
    }
    if (tid < 256) {
        int l = tid >> 7, b = (tid >> 2) & 31, u = tid & 3;
        __stcg(&g_h[l][0][b][j0 + u], h0S[l * HH + j0 + u]);
    }
    grid_sync();

    float* hN = out + (size_t)TT * BB * HH;
    float* cN = hN + 2 * BB * HH;

    for (int t = 0; t < TT; t++) {
        int par = t & 1;
        __syncthreads();  // prior epilogue readers of mS done
        if (tid < 32) mS[tid] = __ldg(rmask + t * BB + tid);
        __syncthreads();  // mS visible before phase1 prefetch
        bool last = (t == TT - 1);

        // phase 1: layer 0. U = x[t], V = masked h_l0(prev)
        phase(sm, mS, h0S,
              x + (size_t)t * BB * II,
              &g_h[0][par][0][0],
              0, 1, 0,
              &g_h[0][par ^ 1][0][0],
              nullptr, hN, cN, last,
              j0, tid, bq, rq, ks);

        grid_sync();

        // phase 2: layer 1. U = fresh h_l0, V = masked h_l1(prev)
        phase(sm, mS, h0S + HH,
              &g_h[0][par ^ 1][0][0],
              &g_h[1][par][0][0],
              2, 3, 1,
              &g_h[1][par ^ 1][0][0],
              out + (size_t)t * BB * HH, hN, cN, last,
              j0, tid, bq, rq, ks);
        // (no end-of-step grid sync needed: parity double-buffering makes the
        //  only cross-block hazards pass through the mid-step sync)
    }
}

extern "C" void kernel_launch(void* const* d_in, const int* in_sizes, int n_in,
                              void* d_out, int out_size) {
    const float* x    = (const float*)d_in[0];
    const int*   rm   = (const int*)d_in[1];
    const float* w_ih = (const float*)d_in[2];
    const float* w_hh = (const float*)d_in[3];
    const float* b_ih = (const float*)d_in[4];
    const float* b_hh = (const float*)d_in[5];
    const float* h0   = (const float*)d_in[6];
    const float* c0   = (const float*)d_in[7];
    float* out = (float*)d_out;

    cudaFuncSetAttribute(lstm_kernel, cudaFuncAttributeMaxDynamicSharedMemorySize, SMEM_BYTES);
    lstm_kernel<<<NBLK, NTH, SMEM_BYTES>>>(x, rm, w_ih, w_hh, b_ih, b_hh, h0, c0, out);
}